// round 7
// baseline (speedup 1.0000x reference)
#include <cuda_runtime.h>
#include <cuda_bf16.h>
#include <mma.h>
#include <math.h>
#include <stdint.h>

using namespace nvcuda;

// 0: x [1024,2560]  1: h [1024,2560,16]  2: W_dt_low [160,2560]  3: W_dt [2560,160]
// 4: b_dt [2560]    5: W_B [16,2560]     6: W_C [16,2560]        7: A_log [2560,16]
// 8: D [2560]       out: y [1024,2560]   all f32

#define B_SZ    1024
#define DIN     2560
#define DST     16
#define DTR     160
#define NPROJ   192
#define KPAD    192
#define SPLITK  8
#define KSPLIT  (DIN / SPLITK)   // 320
#define KC      32
#define PADK    40

// ---------------- device scratch ----------------
__device__ __align__(16) __nv_bfloat16 g_xh[B_SZ * DIN], g_xl[B_SZ * DIN];
__device__ __align__(16) __nv_bfloat16 g_w1h[NPROJ * DIN], g_w1l[NPROJ * DIN];
__device__ __align__(16) __nv_bfloat16 g_w2h[DIN * KPAD], g_w2l[DIN * KPAD];
__device__ __align__(16) __nv_bfloat16 g_ph[B_SZ * KPAD], g_pl[B_SZ * KPAD];
__device__ __align__(16) float g_partial[SPLITK * B_SZ * NPROJ];
__device__ __align__(16) float g_proj[B_SZ * NPROJ];
__device__ __align__(16) float g_A2[DIN * DST];

// ---------------- helpers ----------------
__device__ __forceinline__ void split2(float v, __nv_bfloat16& hi, __nv_bfloat16& lo) {
    hi = __float2bfloat16(v);
    lo = __float2bfloat16(v - __bfloat162float(hi));
}
__device__ __forceinline__ void split_store4(float4 v, __nv_bfloat16* ph, __nv_bfloat16* pl) {
    __nv_bfloat16 h0, h1, h2, h3, l0, l1, l2, l3;
    split2(v.x, h0, l0); split2(v.y, h1, l1); split2(v.z, h2, l2); split2(v.w, h3, l3);
    reinterpret_cast<__nv_bfloat162*>(ph)[0] = __nv_bfloat162(h0, h1);
    reinterpret_cast<__nv_bfloat162*>(ph)[1] = __nv_bfloat162(h2, h3);
    reinterpret_cast<__nv_bfloat162*>(pl)[0] = __nv_bfloat162(l0, l1);
    reinterpret_cast<__nv_bfloat162*>(pl)[1] = __nv_bfloat162(l2, l3);
}
__device__ __forceinline__ void cp16(void* sdst, const void* gsrc) {
    asm volatile("cp.async.cg.shared.global [%0], [%1], 16;"
        :: "r"((uint32_t)__cvta_generic_to_shared(sdst)), "l"(gsrc));
}
#define CP_COMMIT() asm volatile("cp.async.commit_group;" ::: "memory")
#define CP_WAIT(N)  asm volatile("cp.async.wait_group %0;" :: "n"(N) : "memory")

// ---------------- fused prep ----------------
#define PREP_BLOCKS 3560
__global__ __launch_bounds__(256) void prep_all(const float* __restrict__ x,
                                                const float* __restrict__ wdtlow,
                                                const float* __restrict__ wb,
                                                const float* __restrict__ wc,
                                                const float* __restrict__ wdt,
                                                const float* __restrict__ alog) {
    const int bid = blockIdx.x;
    const int tid = threadIdx.x;
    if (bid < 2560) {
        int i = bid * 256 + tid;
        float4 v = reinterpret_cast<const float4*>(x)[i];
        split_store4(v, g_xh + i * 4, g_xl + i * 4);
    } else if (bid < 3040) {
        int i = (bid - 2560) * 256 + tid;
        int n = i / (DIN / 4);
        int j = i % (DIN / 4);
        const float* row = (n < DTR) ? wdtlow + (size_t)n * DIN
                         : (n < DTR + DST) ? wb + (size_t)(n - DTR) * DIN
                         : wc + (size_t)(n - DTR - DST) * DIN;
        float4 v = reinterpret_cast<const float4*>(row)[j];
        split_store4(v, g_w1h + i * 4, g_w1l + i * 4);
    } else if (bid < 3520) {
        int i = (bid - 3040) * 256 + tid;
        int n = i / (KPAD / 4);
        int c4 = (i % (KPAD / 4)) * 4;
        float4 v = (c4 < DTR) ? *reinterpret_cast<const float4*>(wdt + (size_t)n * DTR + c4)
                              : make_float4(0.f, 0.f, 0.f, 0.f);
        split_store4(v, g_w2h + (size_t)n * KPAD + c4, g_w2l + (size_t)n * KPAD + c4);
    } else {
        int i = (bid - 3520) * 256 + tid;
        float4 v = reinterpret_cast<const float4*>(alog)[i];
        float4 o = make_float4(-__expf(v.x), -__expf(v.y), -__expf(v.z), -__expf(v.w));
        reinterpret_cast<float4*>(g_A2)[i] = o;
    }
}

// ---------------- wmma GEMM, cp.async 2-stage; MODE 1 fuses softplus + SSM + y ----------------
#define STAGE_SZ  30720
#define SMEM_DYN0 (2 * STAGE_SZ)          // mode 0
// mode 1 epilogue layout: dtS 34816 | bcS 16384 | a2S 4096 | yS 32768 = 88064
#define SMEM_DYN1 88064

template<int MODE>
__global__ __launch_bounds__(256) void gemm_wmma(const float* __restrict__ bias,
                                                 const float* __restrict__ x,
                                                 const float* __restrict__ hmat,
                                                 const float* __restrict__ Dv,
                                                 float* __restrict__ y) {
    extern __shared__ __align__(16) char smbuf[];
    const int tid = threadIdx.x;
    const int wid = tid >> 5;
    const int wm = wid >> 1;
    const int wn = wid & 1;
    const int mBase = blockIdx.x * 128;
    const int nBase = blockIdx.y * 64;
    const int kOff  = (MODE == 0) ? blockIdx.z * KSPLIT : 0;
    const int nch   = ((MODE == 0) ? KSPLIT : KPAD) / KC;
    const int lda   = (MODE == 0) ? DIN : KPAD;
    const int ldb   = (MODE == 0) ? DIN : KPAD;
    const __nv_bfloat16* aH = (MODE == 0) ? g_xh : g_ph;
    const __nv_bfloat16* aL = (MODE == 0) ? g_xl : g_pl;
    const __nv_bfloat16* bH = (MODE == 0) ? g_w1h : g_w2h;
    const __nv_bfloat16* bL = (MODE == 0) ? g_w1l : g_w2l;

    auto prefetch = [&](int stage, int k0) {
        char* base = smbuf + stage * STAGE_SZ;
        __nv_bfloat16* sAh = reinterpret_cast<__nv_bfloat16*>(base);
        __nv_bfloat16* sAl = reinterpret_cast<__nv_bfloat16*>(base + 10240);
        __nv_bfloat16* sBh = reinterpret_cast<__nv_bfloat16*>(base + 20480);
        __nv_bfloat16* sBl = reinterpret_cast<__nv_bfloat16*>(base + 25600);
#pragma unroll
        for (int s = 0; s < 2; s++) {
            int u = tid + s * 256;
            int row = u >> 2, c16 = u & 3;
            const size_t go = (size_t)(mBase + row) * lda + k0 + c16 * 8;
            cp16(sAh + row * PADK + c16 * 8, aH + go);
            cp16(sAl + row * PADK + c16 * 8, aL + go);
        }
        {
            int row = tid >> 2, c16 = tid & 3;
            const size_t go = (size_t)(nBase + row) * ldb + k0 + c16 * 8;
            cp16(sBh + row * PADK + c16 * 8, bH + go);
            cp16(sBl + row * PADK + c16 * 8, bL + go);
        }
        CP_COMMIT();
    };

    wmma::fragment<wmma::accumulator, 16, 16, 16, float> acc[2][2];
#pragma unroll
    for (int i = 0; i < 2; i++)
#pragma unroll
        for (int j = 0; j < 2; j++) wmma::fill_fragment(acc[i][j], 0.0f);

    prefetch(0, kOff);

    for (int ch = 0; ch < nch; ch++) {
        const int stage = ch & 1;
        if (ch + 1 < nch) {
            prefetch(stage ^ 1, kOff + (ch + 1) * KC);
            CP_WAIT(1);
        } else {
            CP_WAIT(0);
        }
        __syncthreads();

        char* base = smbuf + stage * STAGE_SZ;
        __nv_bfloat16* sAh = reinterpret_cast<__nv_bfloat16*>(base);
        __nv_bfloat16* sAl = reinterpret_cast<__nv_bfloat16*>(base + 10240);
        __nv_bfloat16* sBh = reinterpret_cast<__nv_bfloat16*>(base + 20480);
        __nv_bfloat16* sBl = reinterpret_cast<__nv_bfloat16*>(base + 25600);

#pragma unroll
        for (int kk = 0; kk < 2; kk++) {
            wmma::fragment<wmma::matrix_a, 16, 16, 16, __nv_bfloat16, wmma::row_major> ah[2], al[2];
            wmma::fragment<wmma::matrix_b, 16, 16, 16, __nv_bfloat16, wmma::col_major> bh[2], bl[2];
#pragma unroll
            for (int i = 0; i < 2; i++) {
                wmma::load_matrix_sync(ah[i], sAh + (wm * 32 + i * 16) * PADK + kk * 16, PADK);
                wmma::load_matrix_sync(al[i], sAl + (wm * 32 + i * 16) * PADK + kk * 16, PADK);
            }
#pragma unroll
            for (int j = 0; j < 2; j++) {
                wmma::load_matrix_sync(bh[j], sBh + (wn * 32 + j * 16) * PADK + kk * 16, PADK);
                wmma::load_matrix_sync(bl[j], sBl + (wn * 32 + j * 16) * PADK + kk * 16, PADK);
            }
#pragma unroll
            for (int i = 0; i < 2; i++)
#pragma unroll
                for (int j = 0; j < 2; j++) {
                    wmma::mma_sync(acc[i][j], ah[i], bh[j], acc[i][j]);
                    wmma::mma_sync(acc[i][j], ah[i], bl[j], acc[i][j]);
                    wmma::mma_sync(acc[i][j], al[i], bh[j], acc[i][j]);
                }
        }
        __syncthreads();
    }

    if (MODE == 0) {
        float* base = g_partial + ((size_t)blockIdx.z * B_SZ + mBase) * NPROJ + nBase;
#pragma unroll
        for (int i = 0; i < 2; i++)
#pragma unroll
            for (int j = 0; j < 2; j++) {
                float* p = base + (size_t)(wm * 32 + i * 16) * NPROJ + wn * 32 + j * 16;
                wmma::store_matrix_sync(p, acc[i][j], NPROJ, wmma::mem_row_major);
            }
        return;
    }

    // ================= MODE 1 fused epilogue: softplus + SSM + y =================
    float* dtS = reinterpret_cast<float*>(smbuf);            // [128][68]
    float* bcS = reinterpret_cast<float*>(smbuf + 34816);    // [128][32] Bt|Ct
    float* a2S = reinterpret_cast<float*>(smbuf + 51200);    // [64][16]
    float* yS  = reinterpret_cast<float*>(smbuf + 55296);    // [128][64]

    // dump accumulator fragments
#pragma unroll
    for (int i = 0; i < 2; i++)
#pragma unroll
        for (int j = 0; j < 2; j++) {
            float* p = dtS + (size_t)(wm * 32 + i * 16) * 68 + wn * 32 + j * 16;
            wmma::store_matrix_sync(p, acc[i][j], 68, wmma::mem_row_major);
        }
    __syncthreads();

    // softplus + bias in place  (128 x 16 float4)
#pragma unroll
    for (int s = 0; s < 8; s++) {
        int u = tid + s * 256;
        int row = u >> 4, c4 = (u & 15) * 4;
        float4 v = *reinterpret_cast<float4*>(dtS + row * 68 + c4);
        const int gn = nBase + c4;
        v.x += __ldg(bias + gn);     v.y += __ldg(bias + gn + 1);
        v.z += __ldg(bias + gn + 2); v.w += __ldg(bias + gn + 3);
        float4 o;
        o.x = fmaxf(v.x, 0.f) + log1pf(__expf(-fabsf(v.x)));
        o.y = fmaxf(v.y, 0.f) + log1pf(__expf(-fabsf(v.y)));
        o.z = fmaxf(v.z, 0.f) + log1pf(__expf(-fabsf(v.z)));
        o.w = fmaxf(v.w, 0.f) + log1pf(__expf(-fabsf(v.w)));
        *reinterpret_cast<float4*>(dtS + row * 68 + c4) = o;
    }
    // stage Bt/Ct (128 rows x 8 float4) and A2 (64 rows x 4 float4)
#pragma unroll
    for (int s = 0; s < 4; s++) {
        int u = tid + s * 256;
        int row = u >> 3, c4 = (u & 7) * 4;
        *reinterpret_cast<float4*>(bcS + row * 32 + c4) =
            *reinterpret_cast<const float4*>(g_proj + (size_t)(mBase + row) * NPROJ + DTR + c4);
    }
    {
        int row = tid >> 2, c4 = (tid & 3) * 4;
        *reinterpret_cast<float4*>(a2S + row * 16 + c4) =
            *reinterpret_cast<const float4*>(g_A2 + (size_t)(nBase + row) * DST + c4);
    }
    __syncthreads();

    // SSM sweep: iteration = batch row; 4 lanes per (b,d); 64 d per iteration
    const int l4  = tid & 3;
    const int col = tid >> 2;              // 0..63 local d
    const int d   = nBase + col;
    const float Dval = __ldg(Dv + d);
    const float4 A4 = *reinterpret_cast<const float4*>(a2S + col * 16 + l4 * 4);

#pragma unroll 4
    for (int row = 0; row < 128; row++) {
        const int b = mBase + row;
        const float dtv = dtS[row * 68 + col];
        const float xv  = __ldg(x + (size_t)b * DIN + d);
        const float4 h4 = *reinterpret_cast<const float4*>(hmat + ((size_t)b * DIN + d) * DST + l4 * 4);
        const float4 B4 = *reinterpret_cast<const float4*>(bcS + row * 32 + l4 * 4);
        const float4 C4 = *reinterpret_cast<const float4*>(bcS + row * 32 + 16 + l4 * 4);
        const float dx = dtv * xv;
        float e0 = __expf(dtv * A4.x);
        float e1 = __expf(dtv * A4.y);
        float e2 = __expf(dtv * A4.z);
        float e3 = __expf(dtv * A4.w);
        float hn0 = fmaf(e0, h4.x, dx * B4.x);
        float hn1 = fmaf(e1, h4.y, dx * B4.y);
        float hn2 = fmaf(e2, h4.z, dx * B4.z);
        float hn3 = fmaf(e3, h4.w, dx * B4.w);
        float acc_ = hn0 * C4.x;
        acc_ = fmaf(hn1, C4.y, acc_);
        acc_ = fmaf(hn2, C4.z, acc_);
        acc_ = fmaf(hn3, C4.w, acc_);
        acc_ += __shfl_xor_sync(0xffffffffu, acc_, 1);
        acc_ += __shfl_xor_sync(0xffffffffu, acc_, 2);
        if (l4 == 0) yS[row * 64 + col] = fmaf(Dval, xv, acc_);
    }
    __syncthreads();

    // write y (128 x 16 float4, coalesced)
#pragma unroll
    for (int s = 0; s < 8; s++) {
        int u = tid + s * 256;
        int row = u >> 4, c4 = (u & 15) * 4;
        *reinterpret_cast<float4*>(y + (size_t)(mBase + row) * DIN + nBase + c4) =
            *reinterpret_cast<float4*>(yS + row * 64 + c4);
    }
}

// ---------------- split-K reduce + bf16 split of proj ----------------
__global__ void reduce_kernel() {
    int i = blockIdx.x * blockDim.x + threadIdx.x;
    const int total = B_SZ * NPROJ;
    if (i >= total) return;
    float s = g_partial[i];
#pragma unroll
    for (int z = 1; z < SPLITK; z++) s += g_partial[(size_t)z * total + i];
    g_proj[i] = s;
    __nv_bfloat16 hi, lo;
    split2(s, hi, lo);
    g_ph[i] = hi; g_pl[i] = lo;
}

// ---------------- launch ----------------
extern "C" void kernel_launch(void* const* d_in, const int* in_sizes, int n_in,
                              void* d_out, int out_size) {
    const float* x      = (const float*)d_in[0];
    const float* h      = (const float*)d_in[1];
    const float* wdtlow = (const float*)d_in[2];
    const float* wdt    = (const float*)d_in[3];
    const float* bdt    = (const float*)d_in[4];
    const float* wb     = (const float*)d_in[5];
    const float* wc     = (const float*)d_in[6];
    const float* alog   = (const float*)d_in[7];
    const float* Dv     = (const float*)d_in[8];
    float* y = (float*)d_out;

    cudaFuncSetAttribute(gemm_wmma<0>, cudaFuncAttributeMaxDynamicSharedMemorySize, SMEM_DYN0);
    cudaFuncSetAttribute(gemm_wmma<1>, cudaFuncAttributeMaxDynamicSharedMemorySize, SMEM_DYN1);

    prep_all<<<PREP_BLOCKS, 256>>>(x, wdtlow, wb, wc, wdt, alog);
    gemm_wmma<0><<<dim3(B_SZ / 128, NPROJ / 64, SPLITK), 256, SMEM_DYN0>>>(bdt, nullptr, nullptr, nullptr, nullptr);
    reduce_kernel<<<(B_SZ * NPROJ + 255) / 256, 256>>>();
    gemm_wmma<1><<<dim3(B_SZ / 128, DIN / 64, 1), 256, SMEM_DYN1>>>(bdt, x, h, Dv, y);
}

// round 8
// speedup vs baseline: 1.5182x; 1.5182x over previous
#include <cuda_runtime.h>
#include <cuda_bf16.h>
#include <mma.h>
#include <math.h>
#include <stdint.h>

using namespace nvcuda;

// 0: x [1024,2560]  1: h [1024,2560,16]  2: W_dt_low [160,2560]  3: W_dt [2560,160]
// 4: b_dt [2560]    5: W_B [16,2560]     6: W_C [16,2560]        7: A_log [2560,16]
// 8: D [2560]       out: y [1024,2560]   all f32

#define B_SZ    1024
#define DIN     2560
#define DST     16
#define DTR     160
#define NPROJ   192
#define KPAD    192
#define SPLITK  16
#define KSPLIT  (DIN / SPLITK)   // 160
#define KC      32
#define PADK    40

// ---------------- device scratch ----------------
__device__ __align__(16) __nv_bfloat16 g_xh[B_SZ * DIN], g_xl[B_SZ * DIN];
__device__ __align__(16) __nv_bfloat16 g_w1h[NPROJ * DIN], g_w1l[NPROJ * DIN];
__device__ __align__(16) __nv_bfloat16 g_w2h[DIN * KPAD], g_w2l[DIN * KPAD];
__device__ __align__(16) __nv_bfloat16 g_ph[B_SZ * KPAD], g_pl[B_SZ * KPAD];
__device__ __align__(16) float g_partial[SPLITK * B_SZ * NPROJ];
__device__ __align__(16) float g_proj[B_SZ * NPROJ];
__device__ __align__(16) float g_dt[B_SZ * DIN];
__device__ __align__(16) float g_A2[DIN * DST];

// ---------------- helpers ----------------
__device__ __forceinline__ void split2(float v, __nv_bfloat16& hi, __nv_bfloat16& lo) {
    hi = __float2bfloat16(v);
    lo = __float2bfloat16(v - __bfloat162float(hi));
}
__device__ __forceinline__ void split_store4(float4 v, __nv_bfloat16* ph, __nv_bfloat16* pl) {
    __nv_bfloat16 h0, h1, h2, h3, l0, l1, l2, l3;
    split2(v.x, h0, l0); split2(v.y, h1, l1); split2(v.z, h2, l2); split2(v.w, h3, l3);
    reinterpret_cast<__nv_bfloat162*>(ph)[0] = __nv_bfloat162(h0, h1);
    reinterpret_cast<__nv_bfloat162*>(ph)[1] = __nv_bfloat162(h2, h3);
    reinterpret_cast<__nv_bfloat162*>(pl)[0] = __nv_bfloat162(l0, l1);
    reinterpret_cast<__nv_bfloat162*>(pl)[1] = __nv_bfloat162(l2, l3);
}
__device__ __forceinline__ void cp16(void* sdst, const void* gsrc) {
    asm volatile("cp.async.cg.shared.global [%0], [%1], 16;"
        :: "r"((uint32_t)__cvta_generic_to_shared(sdst)), "l"(gsrc));
}
#define CP_COMMIT() asm volatile("cp.async.commit_group;" ::: "memory")
#define CP_WAIT(N)  asm volatile("cp.async.wait_group %0;" :: "n"(N) : "memory")

// ---------------- fused prep ----------------
#define PREP_BLOCKS 3560
__global__ __launch_bounds__(256) void prep_all(const float* __restrict__ x,
                                                const float* __restrict__ wdtlow,
                                                const float* __restrict__ wb,
                                                const float* __restrict__ wc,
                                                const float* __restrict__ wdt,
                                                const float* __restrict__ alog) {
    const int bid = blockIdx.x;
    const int tid = threadIdx.x;
    if (bid < 2560) {
        int i = bid * 256 + tid;
        float4 v = reinterpret_cast<const float4*>(x)[i];
        split_store4(v, g_xh + i * 4, g_xl + i * 4);
    } else if (bid < 3040) {
        int i = (bid - 2560) * 256 + tid;
        int n = i / (DIN / 4);
        int j = i % (DIN / 4);
        const float* row = (n < DTR) ? wdtlow + (size_t)n * DIN
                         : (n < DTR + DST) ? wb + (size_t)(n - DTR) * DIN
                         : wc + (size_t)(n - DTR - DST) * DIN;
        float4 v = reinterpret_cast<const float4*>(row)[j];
        split_store4(v, g_w1h + i * 4, g_w1l + i * 4);
    } else if (bid < 3520) {
        int i = (bid - 3040) * 256 + tid;
        int n = i / (KPAD / 4);
        int c4 = (i % (KPAD / 4)) * 4;
        float4 v = (c4 < DTR) ? *reinterpret_cast<const float4*>(wdt + (size_t)n * DTR + c4)
                              : make_float4(0.f, 0.f, 0.f, 0.f);
        split_store4(v, g_w2h + (size_t)n * KPAD + c4, g_w2l + (size_t)n * KPAD + c4);
    } else {
        int i = (bid - 3520) * 256 + tid;
        float4 v = reinterpret_cast<const float4*>(alog)[i];
        float4 o = make_float4(-__expf(v.x), -__expf(v.y), -__expf(v.z), -__expf(v.w));
        reinterpret_cast<float4*>(g_A2)[i] = o;
    }
}

// ---------------- wmma GEMM with cp.async 2-stage pipeline ----------------
// CTA: 128m x 64n, 8 warps (4x2), each 32m x 32n = 2x2 frags; 3-term hi/lo split.
#define STAGE_SZ 30720
#define SMEM_DYN (2 * STAGE_SZ)

template<int MODE>
__global__ __launch_bounds__(256, 2) void gemm_wmma(const float* __restrict__ bias) {
    extern __shared__ __align__(16) char smbuf[];
    const int tid = threadIdx.x;
    const int wid = tid >> 5;
    const int wm = wid >> 1;
    const int wn = wid & 1;
    const int mBase = blockIdx.x * 128;
    const int nBase = blockIdx.y * 64;
    const int kOff  = (MODE == 0) ? blockIdx.z * KSPLIT : 0;
    const int nch   = ((MODE == 0) ? KSPLIT : KPAD) / KC;
    const int lda   = (MODE == 0) ? DIN : KPAD;
    const int ldb   = (MODE == 0) ? DIN : KPAD;
    const __nv_bfloat16* aH = (MODE == 0) ? g_xh : g_ph;
    const __nv_bfloat16* aL = (MODE == 0) ? g_xl : g_pl;
    const __nv_bfloat16* bH = (MODE == 0) ? g_w1h : g_w2h;
    const __nv_bfloat16* bL = (MODE == 0) ? g_w1l : g_w2l;

    auto prefetch = [&](int stage, int k0) {
        char* base = smbuf + stage * STAGE_SZ;
        __nv_bfloat16* sAh = reinterpret_cast<__nv_bfloat16*>(base);
        __nv_bfloat16* sAl = reinterpret_cast<__nv_bfloat16*>(base + 10240);
        __nv_bfloat16* sBh = reinterpret_cast<__nv_bfloat16*>(base + 20480);
        __nv_bfloat16* sBl = reinterpret_cast<__nv_bfloat16*>(base + 25600);
#pragma unroll
        for (int s = 0; s < 2; s++) {
            int u = tid + s * 256;
            int row = u >> 2, c16 = u & 3;
            const size_t go = (size_t)(mBase + row) * lda + k0 + c16 * 8;
            cp16(sAh + row * PADK + c16 * 8, aH + go);
            cp16(sAl + row * PADK + c16 * 8, aL + go);
        }
        {
            int row = tid >> 2, c16 = tid & 3;
            const size_t go = (size_t)(nBase + row) * ldb + k0 + c16 * 8;
            cp16(sBh + row * PADK + c16 * 8, bH + go);
            cp16(sBl + row * PADK + c16 * 8, bL + go);
        }
        CP_COMMIT();
    };

    wmma::fragment<wmma::accumulator, 16, 16, 16, float> acc[2][2];
#pragma unroll
    for (int i = 0; i < 2; i++)
#pragma unroll
        for (int j = 0; j < 2; j++) wmma::fill_fragment(acc[i][j], 0.0f);

    prefetch(0, kOff);

    for (int ch = 0; ch < nch; ch++) {
        const int stage = ch & 1;
        if (ch + 1 < nch) {
            prefetch(stage ^ 1, kOff + (ch + 1) * KC);
            CP_WAIT(1);
        } else {
            CP_WAIT(0);
        }
        __syncthreads();

        char* base = smbuf + stage * STAGE_SZ;
        __nv_bfloat16* sAh = reinterpret_cast<__nv_bfloat16*>(base);
        __nv_bfloat16* sAl = reinterpret_cast<__nv_bfloat16*>(base + 10240);
        __nv_bfloat16* sBh = reinterpret_cast<__nv_bfloat16*>(base + 20480);
        __nv_bfloat16* sBl = reinterpret_cast<__nv_bfloat16*>(base + 25600);

#pragma unroll
        for (int kk = 0; kk < 2; kk++) {
            wmma::fragment<wmma::matrix_a, 16, 16, 16, __nv_bfloat16, wmma::row_major> ah[2], al[2];
            wmma::fragment<wmma::matrix_b, 16, 16, 16, __nv_bfloat16, wmma::col_major> bh[2], bl[2];
#pragma unroll
            for (int i = 0; i < 2; i++) {
                wmma::load_matrix_sync(ah[i], sAh + (wm * 32 + i * 16) * PADK + kk * 16, PADK);
                wmma::load_matrix_sync(al[i], sAl + (wm * 32 + i * 16) * PADK + kk * 16, PADK);
            }
#pragma unroll
            for (int j = 0; j < 2; j++) {
                wmma::load_matrix_sync(bh[j], sBh + (wn * 32 + j * 16) * PADK + kk * 16, PADK);
                wmma::load_matrix_sync(bl[j], sBl + (wn * 32 + j * 16) * PADK + kk * 16, PADK);
            }
#pragma unroll
            for (int i = 0; i < 2; i++)
#pragma unroll
                for (int j = 0; j < 2; j++) {
                    wmma::mma_sync(acc[i][j], ah[i], bh[j], acc[i][j]);
                    wmma::mma_sync(acc[i][j], ah[i], bl[j], acc[i][j]);
                    wmma::mma_sync(acc[i][j], al[i], bh[j], acc[i][j]);
                }
        }
        __syncthreads();
    }

    if (MODE == 0) {
        float* base = g_partial + ((size_t)blockIdx.z * B_SZ + mBase) * NPROJ + nBase;
#pragma unroll
        for (int i = 0; i < 2; i++)
#pragma unroll
            for (int j = 0; j < 2; j++) {
                float* p = base + (size_t)(wm * 32 + i * 16) * NPROJ + wn * 32 + j * 16;
                wmma::store_matrix_sync(p, acc[i][j], NPROJ, wmma::mem_row_major);
            }
    } else {
        float* stage = reinterpret_cast<float*>(smbuf);   // 128 x 68 f32 = 34816B < SMEM_DYN
#pragma unroll
        for (int i = 0; i < 2; i++)
#pragma unroll
            for (int j = 0; j < 2; j++) {
                float* p = stage + (size_t)(wm * 32 + i * 16) * 68 + wn * 32 + j * 16;
                wmma::store_matrix_sync(p, acc[i][j], 68, wmma::mem_row_major);
            }
        __syncthreads();
#pragma unroll
        for (int s = 0; s < 8; s++) {
            int u = tid + s * 256;
            int row = u >> 4, c4 = (u & 15) * 4;
            float4 v = *reinterpret_cast<float4*>(stage + row * 68 + c4);
            const int gn = nBase + c4;
            v.x += __ldg(bias + gn);     v.y += __ldg(bias + gn + 1);
            v.z += __ldg(bias + gn + 2); v.w += __ldg(bias + gn + 3);
            float4 o;
            o.x = fmaxf(v.x, 0.f) + log1pf(__expf(-fabsf(v.x)));
            o.y = fmaxf(v.y, 0.f) + log1pf(__expf(-fabsf(v.y)));
            o.z = fmaxf(v.z, 0.f) + log1pf(__expf(-fabsf(v.z)));
            o.w = fmaxf(v.w, 0.f) + log1pf(__expf(-fabsf(v.w)));
            *reinterpret_cast<float4*>(g_dt + (size_t)(mBase + row) * DIN + gn) = o;
        }
    }
}

// ---------------- split-K reduce + bf16 split of proj ----------------
__global__ void reduce_kernel() {
    int i = blockIdx.x * blockDim.x + threadIdx.x;
    const int total = B_SZ * NPROJ;
    if (i >= total) return;
    float s = g_partial[i];
#pragma unroll
    for (int z = 1; z < SPLITK; z++) s += g_partial[(size_t)z * total + i];
    g_proj[i] = s;
    __nv_bfloat16 hi, lo;
    split2(s, hi, lo);
    g_ph[i] = hi; g_pl[i] = lo;
}

// ---------------- elementwise SSM ----------------
__global__ __launch_bounds__(256) void ssm_kernel(const float* __restrict__ x,
                                                  const float* __restrict__ h,
                                                  const float* __restrict__ Dv,
                                                  float* __restrict__ y) {
    __shared__ float ys[64];
    const int b = blockIdx.y;
    const int dBase = blockIdx.x * 64;
    const int tid = threadIdx.x;
    const int l4 = tid & 3;
    const int d = dBase + (tid >> 2);
    const int pair = b * DIN + d;

    const float dt_v = g_dt[pair];
    const float x_v = x[pair];
    const float4 h4  = *reinterpret_cast<const float4*>(h + (size_t)pair * DST + l4 * 4);
    const float4 A4  = *reinterpret_cast<const float4*>(g_A2 + (size_t)d * DST + l4 * 4);
    const float4 Bt4 = *reinterpret_cast<const float4*>(g_proj + (size_t)b * NPROJ + DTR + l4 * 4);
    const float4 Ct4 = *reinterpret_cast<const float4*>(g_proj + (size_t)b * NPROJ + DTR + DST + l4 * 4);

    const float dx = dt_v * x_v;
    float acc;
    {
        float e0 = __expf(dt_v * A4.x);
        float e1 = __expf(dt_v * A4.y);
        float e2 = __expf(dt_v * A4.z);
        float e3 = __expf(dt_v * A4.w);
        float hn0 = fmaf(e0, h4.x, dx * Bt4.x);
        float hn1 = fmaf(e1, h4.y, dx * Bt4.y);
        float hn2 = fmaf(e2, h4.z, dx * Bt4.z);
        float hn3 = fmaf(e3, h4.w, dx * Bt4.w);
        acc = hn0 * Ct4.x;
        acc = fmaf(hn1, Ct4.y, acc);
        acc = fmaf(hn2, Ct4.z, acc);
        acc = fmaf(hn3, Ct4.w, acc);
    }
    acc += __shfl_xor_sync(0xffffffffu, acc, 1);
    acc += __shfl_xor_sync(0xffffffffu, acc, 2);
    if (l4 == 0) ys[tid >> 2] = fmaf(Dv[d], x_v, acc);
    __syncthreads();
    if (tid < 64) y[(size_t)b * DIN + dBase + tid] = ys[tid];
}

// ---------------- launch ----------------
extern "C" void kernel_launch(void* const* d_in, const int* in_sizes, int n_in,
                              void* d_out, int out_size) {
    const float* x      = (const float*)d_in[0];
    const float* h      = (const float*)d_in[1];
    const float* wdtlow = (const float*)d_in[2];
    const float* wdt    = (const float*)d_in[3];
    const float* bdt    = (const float*)d_in[4];
    const float* wb     = (const float*)d_in[5];
    const float* wc     = (const float*)d_in[6];
    const float* alog   = (const float*)d_in[7];
    const float* Dv     = (const float*)d_in[8];
    float* y = (float*)d_out;

    cudaFuncSetAttribute(gemm_wmma<0>, cudaFuncAttributeMaxDynamicSharedMemorySize, SMEM_DYN);
    cudaFuncSetAttribute(gemm_wmma<1>, cudaFuncAttributeMaxDynamicSharedMemorySize, SMEM_DYN);

    prep_all<<<PREP_BLOCKS, 256>>>(x, wdtlow, wb, wc, wdt, alog);
    gemm_wmma<0><<<dim3(B_SZ / 128, NPROJ / 64, SPLITK), 256, SMEM_DYN>>>(bdt);
    reduce_kernel<<<(B_SZ * NPROJ + 255) / 256, 256>>>();
    gemm_wmma<1><<<dim3(B_SZ / 128, DIN / 64, 1), 256, SMEM_DYN>>>(bdt);
    ssm_kernel<<<dim3(DIN / 64, B_SZ), 256>>>(x, h, Dv, y);
}